// round 6
// baseline (speedup 1.0000x reference)
#include <cuda_runtime.h>
#include <cuda_bf16.h>
#include <math.h>
#include <stdint.h>

// Problem constants
#define BTOK   4096
#define DIN    1024
#define DHID   4096
#define DOUT   1024
#define NE     8
#define TOPK   2
#define MAXROWS (BTOK * TOPK)        // 8192 grouped rows, always exact
#define BM     128
#define MAXTILES (MAXROWS / BM + NE) // 72 worst-case m-tiles (128-row tiling)

#define RT_THREADS 256
#define TOK_PER_TH (BTOK / RT_THREADS)   // 16

#define CANARY_F  (-777.0f)
#define CANARY_I  (0x7eadbeef)

// ---------------- device scratch (static: no allocation in kernel_launch) -----
// NOTE: these symbols are ONLY ever referenced from device code. Passing them
// as kernel arguments from host code passes the HOST shadow address, which on
// GB300 (ATS) is silently dereferenceable -> results vanish into host BSS.
__device__ float g_h[MAXROWS * (size_t)DHID];   // 128 MB hidden activations
__device__ float g_y[MAXROWS * (size_t)DOUT];   // 32 MB per-pair outputs
__device__ float g_gates[BTOK * NE];            // full softmax gates (aux loss)
__device__ float g_topw[BTOK * TOPK];
__device__ int   g_topi[BTOK * TOPK];
__device__ int   g_counts[NE];
__device__ int   g_token_of_row[MAXROWS];
__device__ int   g_row_of[BTOK * TOPK];
__device__ float g_usage[NE];

// ---------------- kernels -----------------------------------------------------

// Plant stage canaries (no output sentinel needed anymore).
__global__ void init_kernel() {
    g_topw[0]   = CANARY_F;
    g_topw[1]   = CANARY_F;
    g_counts[0] = CANARY_I;
    g_h[0]      = CANARY_F;
    g_y[0]      = CANARY_F;
    g_usage[0]  = CANARY_F;
}

// One warp per token: gate logits, full softmax (for loss), top-2 + weights.
__global__ void gating_kernel(const float* __restrict__ x,
                              const float* __restrict__ Wg,
                              const float* __restrict__ bg) {
    int gwarp = (blockIdx.x * blockDim.x + threadIdx.x) >> 5;
    int lane  = threadIdx.x & 31;
    if (gwarp >= BTOK) return;
    const float* xr = x + (size_t)gwarp * DIN;

    float acc[NE];
#pragma unroll
    for (int e = 0; e < NE; e++) acc[e] = 0.f;

    for (int i = lane; i < DIN; i += 32) {
        float xv = xr[i];
        const float4* wg4 = (const float4*)(Wg + (size_t)i * NE);
        float4 w0 = wg4[0];
        float4 w1 = wg4[1];
        acc[0] += xv * w0.x; acc[1] += xv * w0.y;
        acc[2] += xv * w0.z; acc[3] += xv * w0.w;
        acc[4] += xv * w1.x; acc[5] += xv * w1.y;
        acc[6] += xv * w1.z; acc[7] += xv * w1.w;
    }
#pragma unroll
    for (int e = 0; e < NE; e++)
#pragma unroll
        for (int o = 16; o > 0; o >>= 1)
            acc[e] += __shfl_xor_sync(0xffffffffu, acc[e], o);

    if (lane == 0) {
        float logit[NE];
#pragma unroll
        for (int e = 0; e < NE; e++) logit[e] = acc[e] + bg[e];

        float mx = logit[0];
#pragma unroll
        for (int e = 1; e < NE; e++) mx = fmaxf(mx, logit[e]);
        float s = 0.f, ex[NE];
#pragma unroll
        for (int e = 0; e < NE; e++) { ex[e] = expf(logit[e] - mx); s += ex[e]; }
        float inv = 1.f / s;
#pragma unroll
        for (int e = 0; e < NE; e++) g_gates[gwarp * NE + e] = ex[e] * inv;

        // top-2 (lowest index wins ties, matching jax.lax.top_k)
        int i0 = 0;
#pragma unroll
        for (int e = 1; e < NE; e++) if (logit[e] > logit[i0]) i0 = e;
        int i1 = -1;
#pragma unroll
        for (int e = 0; e < NE; e++)
            if (e != i0 && (i1 < 0 || logit[e] > logit[i1])) i1 = e;

        float w0 = 1.f / (1.f + expf(logit[i1] - logit[i0]));
        g_topi[gwarp * 2 + 0] = i0;
        g_topi[gwarp * 2 + 1] = i1;
        g_topw[gwarp * 2 + 0] = w0;
        g_topw[gwarp * 2 + 1] = 1.f - w0;
    }
}

// Single block, deterministic routing (histogram + two-level exclusive scan).
__global__ void route_kernel() {
    __shared__ int hist[RT_THREADS][NE];
    __shared__ int offs_sh[NE];
    __shared__ int counts_sh[NE];
    int tid = threadIdx.x;

    int h[NE];
#pragma unroll
    for (int e = 0; e < NE; e++) h[e] = 0;
    int t0 = tid * TOK_PER_TH;
    for (int i = 0; i < TOK_PER_TH; i++) {
        int t = t0 + i;
        h[g_topi[t * 2 + 0]]++;
        h[g_topi[t * 2 + 1]]++;
    }
#pragma unroll
    for (int e = 0; e < NE; e++) hist[tid][e] = h[e];
    __syncthreads();

    if (tid < NE) {
        int e = tid, s = 0;
        for (int j = 0; j < RT_THREADS; j++) {
            int v = hist[j][e];
            hist[j][e] = s;
            s += v;
        }
        counts_sh[e] = s;
        g_counts[e]  = s;
    }
    __syncthreads();

    if (tid == 0) {
        int off = 0;
        for (int e = 0; e < NE; e++) { offs_sh[e] = off; off += counts_sh[e]; }
    }
    __syncthreads();

    int base[NE];
#pragma unroll
    for (int e = 0; e < NE; e++) base[e] = offs_sh[e] + hist[tid][e];

    for (int i = 0; i < TOK_PER_TH; i++) {
        int t = t0 + i;
#pragma unroll
        for (int k = 0; k < TOPK; k++) {
            int e   = g_topi[t * 2 + k];
            int row = base[e]++;
            g_token_of_row[row] = t;
            g_row_of[t * 2 + k] = row;
        }
    }
}

__global__ void usage_kernel() {
    int e = blockIdx.x;
    __shared__ float s[256];
    float acc = 0.f;
    for (int t = threadIdx.x; t < BTOK; t += 256)
        acc += g_gates[t * NE + e];
    s[threadIdx.x] = acc;
    __syncthreads();
    for (int o = 128; o > 0; o >>= 1) {
        if (threadIdx.x < o) s[threadIdx.x] += s[threadIdx.x + o];
        __syncthreads();
    }
    if (threadIdx.x == 0) g_usage[e] = s[0] / (float)BTOK;
}

__global__ void loss_kernel(float* __restrict__ out, int out_size) {
    float s = 0.f;
#pragma unroll
    for (int e = 0; e < NE; e++) { float u = g_usage[e]; s += u * u; }
    if (out_size > BTOK * DOUT) out[BTOK * DOUT] = (float)NE * s;
}

// Grouped GEMM. STAGE=1: A = x (arg, gathered rows), C = g_h, ReLU.
//              STAGE=2: A = g_h (device symbol), C = g_y, no ReLU.
// Scratch pointers are bound INSIDE device code — never passed from host.
template <int KD, int ND, int STAGE>
__global__ void __launch_bounds__(256)
grouped_gemm_kernel(const float* __restrict__ Aext,
                    const float* __restrict__ W,
                    const float* __restrict__ bias) {
    const float* A = (STAGE == 1) ? Aext : (const float*)g_h;
    float*       C = (STAGE == 1) ? g_h : g_y;

    int t = blockIdx.x;

    int e = 0, grow0 = 0, rows = 0;
    {
        int tileacc = 0, off = 0;
        bool found = false;
#pragma unroll
        for (int ee = 0; ee < NE; ee++) {
            int c  = g_counts[ee];
            int nt = (c + BM - 1) / BM;
            if (!found && t < tileacc + nt) {
                found = true;
                e     = ee;
                int rb = (t - tileacc) * BM;
                grow0 = off + rb;
                rows  = min(BM, c - rb);
            }
            tileacc += nt;
            off     += c;
        }
        if (!found) return;
    }

    int n0 = blockIdx.y * 128;

    __shared__ float As[16][BM + 4];   // transposed A tile, padded
    __shared__ float Bs[16][128];

    const float* Wp = W + (size_t)e * KD * ND + n0;

    int tid = threadIdx.x;
    int tx  = tid & 15;
    int ty  = tid >> 4;

    float acc[8][8];
#pragma unroll
    for (int i = 0; i < 8; i++)
#pragma unroll
        for (int j = 0; j < 8; j++) acc[i][j] = 0.f;

    // A loader: thread owns row lm, two float4 chunks along k
    int lm  = tid >> 1;
    int lkq = (tid & 1) * 2;
    bool rvalid = lm < rows;
    const float* Arow;
    if (STAGE == 1) {
        int tok = rvalid ? g_token_of_row[grow0 + lm] : 0;
        Arow = A + (size_t)tok * KD;
    } else {
        Arow = A + (size_t)(grow0 + lm) * KD;
    }

    // B loader: thread owns 8 consecutive floats of one k-row
    int bu  = tid * 2;
    int bk  = bu >> 5;
    int bn4 = bu & 31;

    for (int k0 = 0; k0 < KD; k0 += 16) {
#pragma unroll
        for (int q = 0; q < 2; q++) {
            int kq = lkq + q;
            float4 v = make_float4(0.f, 0.f, 0.f, 0.f);
            if (rvalid) v = *(const float4*)(Arow + k0 + kq * 4);
            As[kq * 4 + 0][lm] = v.x;
            As[kq * 4 + 1][lm] = v.y;
            As[kq * 4 + 2][lm] = v.z;
            As[kq * 4 + 3][lm] = v.w;
        }
        {
            const float* wrow = Wp + (size_t)(k0 + bk) * ND;
            float4 b0 = *(const float4*)(wrow + bn4 * 4);
            float4 b1 = *(const float4*)(wrow + bn4 * 4 + 4);
            *(float4*)&Bs[bk][bn4 * 4]     = b0;
            *(float4*)&Bs[bk][bn4 * 4 + 4] = b1;
        }
        __syncthreads();

#pragma unroll
        for (int k = 0; k < 16; k++) {
            float a[8], b[8];
            *(float4*)(a)     = *(const float4*)&As[k][ty * 8];
            *(float4*)(a + 4) = *(const float4*)&As[k][ty * 8 + 4];
            *(float4*)(b)     = *(const float4*)&Bs[k][tx * 8];
            *(float4*)(b + 4) = *(const float4*)&Bs[k][tx * 8 + 4];
#pragma unroll
            for (int i = 0; i < 8; i++)
#pragma unroll
                for (int j = 0; j < 8; j++)
                    acc[i][j] = fmaf(a[i], b[j], acc[i][j]);
        }
        __syncthreads();
    }

    float bv[8];
    {
        const float* bp = bias + (size_t)e * ND + n0 + tx * 8;
        *(float4*)(bv)     = *(const float4*)bp;
        *(float4*)(bv + 4) = *(const float4*)(bp + 4);
    }
#pragma unroll
    for (int i = 0; i < 8; i++) {
        int m = ty * 8 + i;
        if (m < rows) {
            float* cp = C + (size_t)(grow0 + m) * ND + n0 + tx * 8;
            float4 v0, v1;
            v0.x = acc[i][0] + bv[0]; v0.y = acc[i][1] + bv[1];
            v0.z = acc[i][2] + bv[2]; v0.w = acc[i][3] + bv[3];
            v1.x = acc[i][4] + bv[4]; v1.y = acc[i][5] + bv[5];
            v1.z = acc[i][6] + bv[6]; v1.w = acc[i][7] + bv[7];
            if (STAGE == 1) {
                v0.x = fmaxf(v0.x, 0.f); v0.y = fmaxf(v0.y, 0.f);
                v0.z = fmaxf(v0.z, 0.f); v0.w = fmaxf(v0.w, 0.f);
                v1.x = fmaxf(v1.x, 0.f); v1.y = fmaxf(v1.y, 0.f);
                v1.z = fmaxf(v1.z, 0.f); v1.w = fmaxf(v1.w, 0.f);
            }
            *(float4*)(cp)     = v0;
            *(float4*)(cp + 4) = v1;
        }
    }
}

// out[t] = w0 * y[row0] + w1 * y[row1]
__global__ void combine_kernel(float* __restrict__ out) {
    int t = blockIdx.x;
    int r0 = g_row_of[t * 2 + 0];
    int r1 = g_row_of[t * 2 + 1];
    float w0 = g_topw[t * 2 + 0];
    float w1 = g_topw[t * 2 + 1];
    const float4* y0 = (const float4*)(g_y + (size_t)r0 * DOUT);
    const float4* y1 = (const float4*)(g_y + (size_t)r1 * DOUT);
    float4* o = (float4*)(out + (size_t)t * DOUT);
    for (int j = threadIdx.x; j < DOUT / 4; j += blockDim.x) {
        float4 a = y0[j], b = y1[j];
        float4 r;
        r.x = w0 * a.x + w1 * b.x;
        r.y = w0 * a.y + w1 * b.y;
        r.z = w0 * a.z + w1 * b.z;
        r.w = w0 * a.w + w1 * b.w;
        o[j] = r;
    }
}

// Tripwire: only writes out[0] if a stage canary shows a dead stage.
__global__ void fingerprint_kernel(float* __restrict__ out, int bind_ok) {
    int C = 0;
    if (g_topw[0] == CANARY_F && g_topw[1] == CANARY_F) C |= 1;
    if (g_counts[0] == CANARY_I)                        C |= 2;
    if (g_h[0] == CANARY_F)                             C |= 4;
    if (g_y[0] == CANARY_F)                             C |= 8;
    if (g_usage[0] == CANARY_F)                         C |= 16;
    if (!(C & 2)) {
        int s = 0;
        for (int e = 0; e < NE; e++) s += g_counts[e];
        if (s != MAXROWS) C |= 32;
    }
    if (!bind_ok) C |= 64;
    if (C != 0) out[0] = (float)C * 1e8f;
}

// ---------------- launch -------------------------------------------------------

extern "C" void kernel_launch(void* const* d_in, const int* in_sizes, int n_in,
                              void* d_out, int out_size) {
    const float *x = 0, *Wg = 0, *bg = 0, *W1 = 0, *b1 = 0, *W2 = 0, *b2 = 0;
    for (int i = 0; i < n_in; i++) {
        const float* p = (const float*)d_in[i];
        switch (in_sizes[i]) {
            case BTOK * DIN:        x  = p; break;                        // 4194304
            case NE:                bg = p; break;                        // 8
            case NE * DHID:         b1 = p; break;                        // 32768
            case NE * DIN * DHID:   if (!W1) W1 = p; else W2 = p; break;  // 33554432
            case DIN * NE:          if (!Wg) Wg = p; else b2 = p; break;  // 8192
            default: break;
        }
    }
    int bind_ok = (x && Wg && bg && W1 && b1 && W2 && b2) ? 1 : 0;
    if (!bind_ok) {
        x  = (const float*)d_in[0]; Wg = (const float*)d_in[1];
        bg = (const float*)d_in[2]; W1 = (const float*)d_in[3];
        b1 = (const float*)d_in[4]; W2 = (const float*)d_in[5];
        b2 = (const float*)d_in[6];
    }
    float* out = (float*)d_out;

    init_kernel<<<1, 1>>>();
    gating_kernel<<<BTOK / 8, 256>>>(x, Wg, bg);
    route_kernel<<<1, RT_THREADS>>>();
    usage_kernel<<<NE, 256>>>();
    loss_kernel<<<1, 1>>>(out, out_size);

    grouped_gemm_kernel<DIN, DHID, 1>
        <<<dim3(MAXTILES, DHID / 128), 256>>>(x, W1, b1);
    grouped_gemm_kernel<DHID, DOUT, 2>
        <<<dim3(MAXTILES, DOUT / 128), 256>>>(nullptr, W2, b2);

    combine_kernel<<<BTOK, 256>>>(out);
    fingerprint_kernel<<<1, 1>>>(out, bind_ok);
}

// round 8
// speedup vs baseline: 2.5429x; 2.5429x over previous
#include <cuda_runtime.h>
#include <cuda_bf16.h>
#include <math.h>
#include <stdint.h>

// ---------------- problem constants -------------------------------------------
#define BTOK   4096
#define DIN    1024
#define DHID   4096
#define DOUT   1024
#define NE     8
#define TOPK   2
#define MAXROWS (BTOK * TOPK)          // 8192 grouped rows, always exact
#define BM     128
#define BN     128
#define BK     32
#define MAXTILES (MAXROWS / BM + NE)   // 72 worst-case m-tiles

#define LDE    40                      // smem lead dim in bf16 elems (80 B)
#define LDB    80                      // in bytes

#define RT_THREADS 256
#define TOK_PER_TH (BTOK / RT_THREADS) // 16

// ---------------- device scratch (device-code-only access!) --------------------
__device__ uint32_t g_h_hi[MAXROWS * (size_t)(DHID / 2)]; // bf16x2 hidden hi
__device__ uint32_t g_h_lo[MAXROWS * (size_t)(DHID / 2)]; // bf16x2 hidden lo
__device__ float    g_y[MAXROWS * (size_t)DOUT];
__device__ float    g_gates[BTOK * NE];
__device__ float    g_topw[BTOK * TOPK];
__device__ int      g_topi[BTOK * TOPK];
__device__ int      g_counts[NE];
__device__ int      g_token_of_row[MAXROWS];
__device__ int      g_row_of[BTOK * TOPK];
__device__ float    g_usage[NE];

// ---------------- helpers -------------------------------------------------------
__device__ __forceinline__ uint32_t smem_u32(const void* p) {
    uint32_t a;
    asm("{ .reg .u64 t; cvta.to.shared.u64 t, %1; cvt.u32.u64 %0, t; }"
        : "=r"(a) : "l"(p));
    return a;
}

__device__ __forceinline__ void ldsm4(uint32_t* r, uint32_t addr) {
    asm volatile("ldmatrix.sync.aligned.m8n8.x4.shared.b16 {%0,%1,%2,%3}, [%4];"
                 : "=r"(r[0]), "=r"(r[1]), "=r"(r[2]), "=r"(r[3]) : "r"(addr));
}

__device__ __forceinline__ void mma_bf16(float* c, const uint32_t* a,
                                         uint32_t b0, uint32_t b1) {
    asm volatile(
        "mma.sync.aligned.m16n8k16.row.col.f32.bf16.bf16.f32 "
        "{%0,%1,%2,%3}, {%4,%5,%6,%7}, {%8,%9}, {%0,%1,%2,%3};"
        : "+f"(c[0]), "+f"(c[1]), "+f"(c[2]), "+f"(c[3])
        : "r"(a[0]), "r"(a[1]), "r"(a[2]), "r"(a[3]), "r"(b0), "r"(b1));
}

#define STS128(addr, r0, r1, r2, r3) \
    asm volatile("st.shared.v4.b32 [%0], {%1, %2, %3, %4};" \
                 :: "r"(addr), "r"(r0), "r"(r1), "r"(r2), "r"(r3))

__device__ __forceinline__ uint32_t bf2u(__nv_bfloat162 h) {
    return *reinterpret_cast<uint32_t*>(&h);
}

// split two fp32 into packed bf16x2 hi and lo words (lo = residual)
__device__ __forceinline__ void split2(float a, float b, uint32_t& hi, uint32_t& lo) {
    __nv_bfloat162 hp = __floats2bfloat162_rn(a, b);
    float la = a - __bfloat162float(hp.x);
    float lb = b - __bfloat162float(hp.y);
    __nv_bfloat162 lp = __floats2bfloat162_rn(la, lb);
    hi = bf2u(hp);
    lo = bf2u(lp);
}

// ---------------- gating / routing / loss --------------------------------------

__global__ void gating_kernel(const float* __restrict__ x,
                              const float* __restrict__ Wg,
                              const float* __restrict__ bg) {
    int gwarp = (blockIdx.x * blockDim.x + threadIdx.x) >> 5;
    int lane  = threadIdx.x & 31;
    if (gwarp >= BTOK) return;
    const float* xr = x + (size_t)gwarp * DIN;

    float acc[NE];
#pragma unroll
    for (int e = 0; e < NE; e++) acc[e] = 0.f;

    for (int i = lane; i < DIN; i += 32) {
        float xv = xr[i];
        const float4* wg4 = (const float4*)(Wg + (size_t)i * NE);
        float4 w0 = wg4[0];
        float4 w1 = wg4[1];
        acc[0] += xv * w0.x; acc[1] += xv * w0.y;
        acc[2] += xv * w0.z; acc[3] += xv * w0.w;
        acc[4] += xv * w1.x; acc[5] += xv * w1.y;
        acc[6] += xv * w1.z; acc[7] += xv * w1.w;
    }
#pragma unroll
    for (int e = 0; e < NE; e++)
#pragma unroll
        for (int o = 16; o > 0; o >>= 1)
            acc[e] += __shfl_xor_sync(0xffffffffu, acc[e], o);

    if (lane == 0) {
        float logit[NE];
#pragma unroll
        for (int e = 0; e < NE; e++) logit[e] = acc[e] + bg[e];

        float mx = logit[0];
#pragma unroll
        for (int e = 1; e < NE; e++) mx = fmaxf(mx, logit[e]);
        float s = 0.f, ex[NE];
#pragma unroll
        for (int e = 0; e < NE; e++) { ex[e] = expf(logit[e] - mx); s += ex[e]; }
        float inv = 1.f / s;
#pragma unroll
        for (int e = 0; e < NE; e++) g_gates[gwarp * NE + e] = ex[e] * inv;

        int i0 = 0;
#pragma unroll
        for (int e = 1; e < NE; e++) if (logit[e] > logit[i0]) i0 = e;
        int i1 = -1;
#pragma unroll
        for (int e = 0; e < NE; e++)
            if (e != i0 && (i1 < 0 || logit[e] > logit[i1])) i1 = e;

        float w0 = 1.f / (1.f + expf(logit[i1] - logit[i0]));
        g_topi[gwarp * 2 + 0] = i0;
        g_topi[gwarp * 2 + 1] = i1;
        g_topw[gwarp * 2 + 0] = w0;
        g_topw[gwarp * 2 + 1] = 1.f - w0;
    }
}

__global__ void route_kernel() {
    __shared__ int hist[RT_THREADS][NE];
    __shared__ int offs_sh[NE];
    __shared__ int counts_sh[NE];
    int tid = threadIdx.x;

    int h[NE];
#pragma unroll
    for (int e = 0; e < NE; e++) h[e] = 0;
    int t0 = tid * TOK_PER_TH;
    for (int i = 0; i < TOK_PER_TH; i++) {
        int t = t0 + i;
        h[g_topi[t * 2 + 0]]++;
        h[g_topi[t * 2 + 1]]++;
    }
#pragma unroll
    for (int e = 0; e < NE; e++) hist[tid][e] = h[e];
    __syncthreads();

    if (tid < NE) {
        int e = tid, s = 0;
        for (int j = 0; j < RT_THREADS; j++) {
            int v = hist[j][e];
            hist[j][e] = s;
            s += v;
        }
        counts_sh[e] = s;
        g_counts[e]  = s;
    }
    __syncthreads();

    if (tid == 0) {
        int off = 0;
        for (int e = 0; e < NE; e++) { offs_sh[e] = off; off += counts_sh[e]; }
    }
    __syncthreads();

    int base[NE];
#pragma unroll
    for (int e = 0; e < NE; e++) base[e] = offs_sh[e] + hist[tid][e];

    for (int i = 0; i < TOK_PER_TH; i++) {
        int t = t0 + i;
#pragma unroll
        for (int k = 0; k < TOPK; k++) {
            int e   = g_topi[t * 2 + k];
            int row = base[e]++;
            g_token_of_row[row] = t;
            g_row_of[t * 2 + k] = row;
        }
    }
}

__global__ void usage_kernel() {
    int e = blockIdx.x;
    __shared__ float s[256];
    float acc = 0.f;
    for (int t = threadIdx.x; t < BTOK; t += 256)
        acc += g_gates[t * NE + e];
    s[threadIdx.x] = acc;
    __syncthreads();
    for (int o = 128; o > 0; o >>= 1) {
        if (threadIdx.x < o) s[threadIdx.x] += s[threadIdx.x + o];
        __syncthreads();
    }
    if (threadIdx.x == 0) g_usage[e] = s[0] / (float)BTOK;
}

__global__ void loss_kernel(float* __restrict__ out, int out_size) {
    float s = 0.f;
#pragma unroll
    for (int e = 0; e < NE; e++) { float u = g_usage[e]; s += u * u; }
    if (out_size > BTOK * DOUT) out[BTOK * DOUT] = (float)NE * s;
}

// ---------------- grouped GEMM via mma.sync (HMMA), split-bf16 3-pass -----------
// STAGE=1: A = x (gathered fp32, split on load) -> g_h hi/lo (bf16x2), ReLU.
// STAGE=2: A = g_h hi/lo (pre-split)            -> g_y (fp32).
template <int KD, int ND, int STAGE>
__global__ void __launch_bounds__(256)
moe_gemm_mma(const float* __restrict__ Aext,
             const float* __restrict__ W,
             const float* __restrict__ bias) {
    int t = blockIdx.x;

    int e = 0, grow0 = 0, rows = 0;
    {
        int tileacc = 0, off = 0;
        bool found = false;
#pragma unroll
        for (int ee = 0; ee < NE; ee++) {
            int c  = g_counts[ee];
            int nt = (c + BM - 1) / BM;
            if (!found && t < tileacc + nt) {
                found = true;
                e     = ee;
                int rb = (t - tileacc) * BM;
                grow0 = off + rb;
                rows  = min(BM, c - rb);
            }
            tileacc += nt;
            off     += c;
        }
        if (!found) return;
    }
    int n0 = blockIdx.y * BN;

    __shared__ __align__(16) uint16_t sAh[BM * LDE];
    __shared__ __align__(16) uint16_t sAl[BM * LDE];
    __shared__ __align__(16) uint16_t sBh[BN * LDE];
    __shared__ __align__(16) uint16_t sBl[BN * LDE];
    uint32_t Ah_b = smem_u32(sAh), Al_b = smem_u32(sAl);
    uint32_t Bh_b = smem_u32(sBh), Bl_b = smem_u32(sBl);

    int tid = threadIdx.x, wid = tid >> 5, lane = tid & 31;
    int warp_m = wid & 3;        // 0..3 -> m offset *32
    int warp_n = wid >> 2;       // 0..1 -> n offset *64

    // ---- global loader mapping ----
    // A: thread -> (row, k-half of 16)
    int arow = tid >> 1, khalf = tid & 1;
    bool rvalid = arow < rows;
    const float* Arow = nullptr;
    const uint4 *Ah4 = nullptr, *Al4 = nullptr;
    if (STAGE == 1) {
        int tok = rvalid ? g_token_of_row[grow0 + arow] : 0;
        Arow = Aext + (size_t)tok * KD;
    } else {
        size_t rb = (size_t)(rvalid ? (grow0 + arow) : 0) * (KD / 2) / 4; // uint4 units
        Ah4 = ((const uint4*)g_h_hi) + rb;
        Al4 = ((const uint4*)g_h_lo) + rb;
    }
    // B: thread -> (n column, k-quarter of 16)
    int bn_l = tid & 127, bkq = (tid >> 7) * 16;
    const float* Wp = W + (size_t)e * KD * ND + n0 + bn_l;

    // ---- ldmatrix address bases ----
    int alr = lane & 15, alc = lane >> 4;
    uint32_t a_off = (uint32_t)(warp_m * 32 + alr) * LDB + (uint32_t)alc * 16;
    int bnr = (lane & 7) + ((lane >> 4) & 1) * 8;
    int bkr = ((lane >> 3) & 1) * 8;
    uint32_t b_off = (uint32_t)(warp_n * 64 + bnr) * LDB + (uint32_t)bkr * 2;

    float acc[2][8][4];
#pragma unroll
    for (int i = 0; i < 2; i++)
#pragma unroll
        for (int j = 0; j < 8; j++)
#pragma unroll
            for (int q = 0; q < 4; q++) acc[i][j][q] = 0.f;

    // staged global data
    float4 av[4];
    uint4  ahv[2], alv[2];
    float  bv[16];

    const int NCH = KD / BK;

    // prefetch chunk 0
    {
        if (STAGE == 1) {
            if (rvalid) {
                const float4* p = (const float4*)(Arow + khalf * 16);
#pragma unroll
                for (int q = 0; q < 4; q++) av[q] = p[q];
            } else {
#pragma unroll
                for (int q = 0; q < 4; q++) av[q] = make_float4(0, 0, 0, 0);
            }
        } else {
            int idx = khalf * 2;  // uint4 index within row (16 bf16 = 2 uint4)
            if (rvalid) {
                ahv[0] = Ah4[idx]; ahv[1] = Ah4[idx + 1];
                alv[0] = Al4[idx]; alv[1] = Al4[idx + 1];
            } else {
                ahv[0] = ahv[1] = alv[0] = alv[1] = make_uint4(0, 0, 0, 0);
            }
        }
#pragma unroll
        for (int j = 0; j < 16; j++)
            bv[j] = Wp[(size_t)(bkq + j) * ND];
    }

    for (int it = 0; it < NCH; it++) {
        __syncthreads();   // all warps done reading smem from previous chunk

        // ---- store staged chunk `it` to smem (split fp32 -> bf16 hi/lo) ----
        {
            uint32_t hi[8], lo[8];
            if (STAGE == 1) {
                split2(av[0].x, av[0].y, hi[0], lo[0]);
                split2(av[0].z, av[0].w, hi[1], lo[1]);
                split2(av[1].x, av[1].y, hi[2], lo[2]);
                split2(av[1].z, av[1].w, hi[3], lo[3]);
                split2(av[2].x, av[2].y, hi[4], lo[4]);
                split2(av[2].z, av[2].w, hi[5], lo[5]);
                split2(av[3].x, av[3].y, hi[6], lo[6]);
                split2(av[3].z, av[3].w, hi[7], lo[7]);
            } else {
                hi[0] = ahv[0].x; hi[1] = ahv[0].y; hi[2] = ahv[0].z; hi[3] = ahv[0].w;
                hi[4] = ahv[1].x; hi[5] = ahv[1].y; hi[6] = ahv[1].z; hi[7] = ahv[1].w;
                lo[0] = alv[0].x; lo[1] = alv[0].y; lo[2] = alv[0].z; lo[3] = alv[0].w;
                lo[4] = alv[1].x; lo[5] = alv[1].y; lo[6] = alv[1].z; lo[7] = alv[1].w;
            }
            uint32_t aaddr = (uint32_t)arow * LDB + (uint32_t)khalf * 32;
            STS128(Ah_b + aaddr,      hi[0], hi[1], hi[2], hi[3]);
            STS128(Ah_b + aaddr + 16, hi[4], hi[5], hi[6], hi[7]);
            STS128(Al_b + aaddr,      lo[0], lo[1], lo[2], lo[3]);
            STS128(Al_b + aaddr + 16, lo[4], lo[5], lo[6], lo[7]);
        }
        {
            uint32_t hi[8], lo[8];
#pragma unroll
            for (int q = 0; q < 8; q++)
                split2(bv[2 * q], bv[2 * q + 1], hi[q], lo[q]);
            uint32_t baddr = (uint32_t)bn_l * LDB + (uint32_t)bkq * 2;
            STS128(Bh_b + baddr,      hi[0], hi[1], hi[2], hi[3]);
            STS128(Bh_b + baddr + 16, hi[4], hi[5], hi[6], hi[7]);
            STS128(Bl_b + baddr,      lo[0], lo[1], lo[2], lo[3]);
            STS128(Bl_b + baddr + 16, lo[4], lo[5], lo[6], lo[7]);
        }
        __syncthreads();

        // ---- prefetch chunk it+1 (LDG in flight during mma) ----
        if (it + 1 < NCH) {
            int k0 = (it + 1) * BK;
            if (STAGE == 1) {
                if (rvalid) {
                    const float4* p = (const float4*)(Arow + k0 + khalf * 16);
#pragma unroll
                    for (int q = 0; q < 4; q++) av[q] = p[q];
                }
            } else {
                int idx = (k0 >> 3) + khalf * 2;
                if (rvalid) {
                    ahv[0] = Ah4[idx]; ahv[1] = Ah4[idx + 1];
                    alv[0] = Al4[idx]; alv[1] = Al4[idx + 1];
                }
            }
#pragma unroll
            for (int j = 0; j < 16; j++)
                bv[j] = Wp[(size_t)(k0 + bkq + j) * ND];
        }

        // ---- mma on chunk it: 2 k-steps x 3 passes ----
#pragma unroll
        for (int h = 0; h < 2; h++) {
            uint32_t fAh[2][4], fAl[2][4];
#pragma unroll
            for (int mi = 0; mi < 2; mi++) {
                uint32_t ad = a_off + (uint32_t)mi * (16 * LDB) + (uint32_t)h * 32;
                ldsm4(fAh[mi], Ah_b + ad);
                ldsm4(fAl[mi], Al_b + ad);
            }
            uint32_t fBh[4][4], fBl[4][4];
#pragma unroll
            for (int n2 = 0; n2 < 4; n2++) {
                uint32_t bd = b_off + (uint32_t)n2 * (16 * LDB) + (uint32_t)h * 32;
                ldsm4(fBh[n2], Bh_b + bd);
                ldsm4(fBl[n2], Bl_b + bd);
            }
#pragma unroll
            for (int mi = 0; mi < 2; mi++)
#pragma unroll
                for (int n2 = 0; n2 < 4; n2++) {
                    // hi*hi
                    mma_bf16(acc[mi][2 * n2],     fAh[mi], fBh[n2][0], fBh[n2][1]);
                    mma_bf16(acc[mi][2 * n2 + 1], fAh[mi], fBh[n2][2], fBh[n2][3]);
                    // hi*lo
                    mma_bf16(acc[mi][2 * n2],     fAh[mi], fBl[n2][0], fBl[n2][1]);
                    mma_bf16(acc[mi][2 * n2 + 1], fAh[mi], fBl[n2][2], fBl[n2][3]);
                    // lo*hi
                    mma_bf16(acc[mi][2 * n2],     fAl[mi], fBh[n2][0], fBh[n2][1]);
                    mma_bf16(acc[mi][2 * n2 + 1], fAl[mi], fBh[n2][2], fBh[n2][3]);
                }
        }
    }

    // ---- epilogue ----
#pragma unroll
    for (int mi = 0; mi < 2; mi++) {
        int m_lo = warp_m * 32 + mi * 16 + (lane >> 2);
#pragma unroll
        for (int ni = 0; ni < 8; ni++) {
            int ncol = warp_n * 64 + ni * 8 + 2 * (lane & 3);
            float b0 = bias[(size_t)e * ND + n0 + ncol];
            float b1 = bias[(size_t)e * ND + n0 + ncol + 1];
#pragma unroll
            for (int half = 0; half < 2; half++) {
                int m = m_lo + half * 8;
                if (m < rows) {
                    float v0 = acc[mi][ni][2 * half]     + b0;
                    float v1 = acc[mi][ni][2 * half + 1] + b1;
                    size_t grow = (size_t)(grow0 + m);
                    if (STAGE == 1) {
                        v0 = fmaxf(v0, 0.f);
                        v1 = fmaxf(v1, 0.f);
                        uint32_t hw, lw;
                        split2(v0, v1, hw, lw);
                        size_t hidx = grow * (ND / 2) + (size_t)(n0 + ncol) / 2;
                        g_h_hi[hidx] = hw;
                        g_h_lo[hidx] = lw;
                    } else {
                        float* cp = g_y + grow * ND + n0 + ncol;
                        cp[0] = v0;
                        cp[1] = v1;
                    }
                }
            }
        }
    }
}

// out[t] = w0 * y[row0] + w1 * y[row1]
__global__ void combine_kernel(float* __restrict__ out) {
    int t = blockIdx.x;
    int r0 = g_row_of[t * 2 + 0];
    int r1 = g_row_of[t * 2 + 1];
    float w0 = g_topw[t * 2 + 0];
    float w1 = g_topw[t * 2 + 1];
    const float4* y0 = (const float4*)(g_y + (size_t)r0 * DOUT);
    const float4* y1 = (const float4*)(g_y + (size_t)r1 * DOUT);
    float4* o = (float4*)(out + (size_t)t * DOUT);
    for (int j = threadIdx.x; j < DOUT / 4; j += blockDim.x) {
        float4 a = y0[j], b = y1[j];
        float4 r;
        r.x = w0 * a.x + w1 * b.x;
        r.y = w0 * a.y + w1 * b.y;
        r.z = w0 * a.z + w1 * b.z;
        r.w = w0 * a.w + w1 * b.w;
        o[j] = r;
    }
}

// ---------------- launch ---------------------------------------------------------

extern "C" void kernel_launch(void* const* d_in, const int* in_sizes, int n_in,
                              void* d_out, int out_size) {
    const float *x = 0, *Wg = 0, *bg = 0, *W1 = 0, *b1 = 0, *W2 = 0, *b2 = 0;
    for (int i = 0; i < n_in; i++) {
        const float* p = (const float*)d_in[i];
        switch (in_sizes[i]) {
            case BTOK * DIN:        x  = p; break;                        // 4194304
            case NE:                bg = p; break;                        // 8
            case NE * DHID:         b1 = p; break;                        // 32768
            case NE * DIN * DHID:   if (!W1) W1 = p; else W2 = p; break;  // 33554432
            case DIN * NE:          if (!Wg) Wg = p; else b2 = p; break;  // 8192
            default: break;
        }
    }
    if (!(x && Wg && bg && W1 && b1 && W2 && b2)) {
        x  = (const float*)d_in[0]; Wg = (const float*)d_in[1];
        bg = (const float*)d_in[2]; W1 = (const float*)d_in[3];
        b1 = (const float*)d_in[4]; W2 = (const float*)d_in[5];
        b2 = (const float*)d_in[6];
    }
    float* out = (float*)d_out;

    gating_kernel<<<BTOK / 8, 256>>>(x, Wg, bg);
    route_kernel<<<1, RT_THREADS>>>();
    usage_kernel<<<NE, 256>>>();
    loss_kernel<<<1, 1>>>(out, out_size);

    moe_gemm_mma<DIN, DHID, 1>
        <<<dim3(MAXTILES, DHID / BN), 256>>>(x, W1, b1);
    moe_gemm_mma<DHID, DOUT, 2>
        <<<dim3(MAXTILES, DOUT / BN), 256>>>(nullptr, W2, b2);

    combine_kernel<<<BTOK, 256>>>(out);
}